// round 1
// baseline (speedup 1.0000x reference)
#include <cuda_runtime.h>
#include <cstdint>

#define SEQ   2048
#define DMODEL 4096
#define NHEAD 32
#define HDIM  128
#define QCD   1536
#define KCD   512
#define RDIM  64
#define HCOLS (QCD + 2*KCD + RDIM)   // 2624
#define QUPN  (DMODEL + RDIM)        // 4160
#define KVN   (2*DMODEL)             // 8192
#define ATT_SCALE 0.07216878364870323f

// ---------------- scratch (device globals; no runtime allocation) ----------------
__device__ float g_h  [SEQ * HCOLS];   // hidden @ w_down
__device__ float g_qqr[SEQ * QUPN];    // cq @ w_q_up  (q | q_rope_raw)
__device__ float g_kv [SEQ * KVN];     // ckv @ w_kv_up (k | v)
__device__ float g_qr [SEQ * RDIM];    // roped q_rope
__device__ float g_kr [SEQ * RDIM];    // roped k_rope
__device__ float g_att[SEQ * DMODEL];  // attention output, (s, h*128+d)

// ---------------- generic SGEMM: C[M,N] = A[M,K] @ B[K,N], row-major ----------------
// Block tile 128x64x8, 256 threads, 8x4 per-thread micro-tile.
// Requires: M%128==0, N%64==0, K%8==0, lda/ldb/ldc %4==0 (true for all calls).
__global__ void __launch_bounds__(256)
sgemm_kernel(const float* __restrict__ A, int lda,
             const float* __restrict__ B, int ldb,
             float* __restrict__ C, int ldc,
             int M, int N, int K)
{
    __shared__ float As[8][128];
    __shared__ float Bs[8][64];

    const int tid = threadIdx.x;
    const int tx  = tid & 15;      // 0..15 -> n
    const int ty  = tid >> 4;      // 0..15 -> m
    const int m0  = blockIdx.y * 128;
    const int n0  = blockIdx.x * 64;

    // A loader: thread t loads one float4 of row (t>>1), k-quad (t&1)
    const int arow = tid >> 1;
    const int akp  = (tid & 1) * 4;
    const float* Arow = A + (size_t)(m0 + arow) * lda + akp;

    // B loader: threads 0..127, row (t>>4), col-quad (t&15)
    const int bkk = tid >> 4;          // 0..15 (only <8 used)
    const int bn4 = (tid & 15) * 4;
    const float* Brow = B + (size_t)bkk * ldb + n0 + bn4;

    float acc[8][4];
    #pragma unroll
    for (int i = 0; i < 8; i++)
        #pragma unroll
        for (int j = 0; j < 4; j++) acc[i][j] = 0.f;

    for (int k0 = 0; k0 < K; k0 += 8) {
        float4 av = *(const float4*)(Arow + k0);
        As[akp + 0][arow] = av.x;
        As[akp + 1][arow] = av.y;
        As[akp + 2][arow] = av.z;
        As[akp + 3][arow] = av.w;
        if (tid < 128) {
            float4 bv = *(const float4*)(Brow + (size_t)k0 * ldb);
            *(float4*)&Bs[bkk][bn4] = bv;
        }
        __syncthreads();

        #pragma unroll
        for (int kk = 0; kk < 8; kk++) {
            float4 a0 = *(const float4*)&As[kk][ty * 8];
            float4 a1 = *(const float4*)&As[kk][ty * 8 + 4];
            float4 bv = *(const float4*)&Bs[kk][tx * 4];
            float a[8] = {a0.x, a0.y, a0.z, a0.w, a1.x, a1.y, a1.z, a1.w};
            float b[4] = {bv.x, bv.y, bv.z, bv.w};
            #pragma unroll
            for (int i = 0; i < 8; i++)
                #pragma unroll
                for (int j = 0; j < 4; j++)
                    acc[i][j] += a[i] * b[j];
        }
        __syncthreads();
    }

    #pragma unroll
    for (int i = 0; i < 8; i++) {
        float4 r = make_float4(acc[i][0], acc[i][1], acc[i][2], acc[i][3]);
        *(float4*)&C[(size_t)(m0 + ty * 8 + i) * ldc + n0 + tx * 4] = r;
    }
}

// ---------------- RoPE on q_rope (from g_qqr) and k_rope (from g_h) ----------------
__global__ void rope_kernel(const float* __restrict__ qqr,
                            const float* __restrict__ h,
                            const float* __restrict__ cosp,
                            const float* __restrict__ sinp,
                            float* __restrict__ qr,
                            float* __restrict__ kr)
{
    int s = blockIdx.x;
    int i = threadIdx.x;                     // 0..63
    float c = cosp[s * RDIM + i];
    float sv = sinp[s * RDIM + i];

    const float* qsrc = qqr + (size_t)s * QUPN + DMODEL;
    const float* ksrc = h   + (size_t)s * HCOLS + (QCD + 2 * KCD);

    float xq = qsrc[i];
    float xk = ksrc[i];
    float rq = (i < 32) ? -qsrc[i + 32] : qsrc[i - 32];
    float rk = (i < 32) ? -ksrc[i + 32] : ksrc[i - 32];

    qr[s * RDIM + i] = xq * c + rq * sv;
    kr[s * RDIM + i] = xk * c + rk * sv;
}

// ---------------- flash attention, fp32, causal, dq=192 dv=128 ----------------
#define QS 196     // row stride of Q/K tiles (192 + 4 pad)
#define VSR 132    // row stride of V tile
#define PSR 68     // row stride of P tile
#define ATTN_SMEM ((64*QS*2 + 64*VSR + 64*PSR) * 4)   // 151552 bytes

__global__ void __launch_bounds__(256)
attn_kernel(const float* __restrict__ qqr,
            const float* __restrict__ kv,
            const float* __restrict__ qr,
            const float* __restrict__ kr,
            float* __restrict__ attout)
{
    extern __shared__ float smem[];
    float* Qs  = smem;                 // [64][QS]
    float* Ks  = Qs  + 64 * QS;        // [64][QS]
    float* Vsh = Ks  + 64 * QS;        // [64][VSR]
    float* Psh = Vsh + 64 * VSR;       // [64][PSR]

    const int qt = 31 - blockIdx.x;    // longest-running tiles scheduled first
    const int hh = blockIdx.y;
    const int tid = threadIdx.x;
    const int tx  = tid & 15;
    const int ty  = tid >> 4;

    // ---- load Q tile (scaled): rows 64, 48 float4 per row (128 nope + 64 rope)
    for (int idx = tid; idx < 64 * 48; idx += 256) {
        int r  = idx / 48;
        int c4 = idx % 48;
        int s  = qt * 64 + r;
        float4 v;
        if (c4 < 32) v = *(const float4*)(qqr + (size_t)s * QUPN + hh * HDIM + c4 * 4);
        else         v = *(const float4*)(qr + (size_t)s * RDIM + (c4 - 32) * 4);
        v.x *= ATT_SCALE; v.y *= ATT_SCALE; v.z *= ATT_SCALE; v.w *= ATT_SCALE;
        *(float4*)&Qs[r * QS + c4 * 4] = v;
    }

    float o[4][8];
    #pragma unroll
    for (int i = 0; i < 4; i++)
        #pragma unroll
        for (int c = 0; c < 8; c++) o[i][c] = 0.f;
    float mi[4] = {-1e30f, -1e30f, -1e30f, -1e30f};
    float li[4] = {0.f, 0.f, 0.f, 0.f};

    for (int j = 0; j <= qt; j++) {
        __syncthreads();   // prior-iter V/P reads complete before overwrite

        // ---- load K tile (nope+rope) and V tile
        for (int idx = tid; idx < 64 * 48; idx += 256) {
            int r  = idx / 48;
            int c4 = idx % 48;
            int s  = j * 64 + r;
            float4 v;
            if (c4 < 32) v = *(const float4*)(kv + (size_t)s * KVN + hh * HDIM + c4 * 4);
            else         v = *(const float4*)(kr + (size_t)s * RDIM + (c4 - 32) * 4);
            *(float4*)&Ks[r * QS + c4 * 4] = v;
        }
        for (int idx = tid; idx < 64 * 32; idx += 256) {
            int r  = idx / 32;
            int c4 = idx % 32;
            int s  = j * 64 + r;
            *(float4*)&Vsh[r * VSR + c4 * 4] =
                *(const float4*)(kv + (size_t)s * KVN + DMODEL + hh * HDIM + c4 * 4);
        }
        __syncthreads();

        // ---- S = Q @ K^T  (4x4 per thread over 192-dot)
        float S[4][4];
        #pragma unroll
        for (int i = 0; i < 4; i++)
            #pragma unroll
            for (int jx = 0; jx < 4; jx++) S[i][jx] = 0.f;

        #pragma unroll 4
        for (int kk = 0; kk < 48; kk++) {
            float4 qa[4], kb[4];
            #pragma unroll
            for (int i = 0; i < 4; i++)
                qa[i] = *(const float4*)&Qs[(ty * 4 + i) * QS + kk * 4];
            #pragma unroll
            for (int jx = 0; jx < 4; jx++)
                kb[jx] = *(const float4*)&Ks[(tx * 4 + jx) * QS + kk * 4];
            #pragma unroll
            for (int i = 0; i < 4; i++)
                #pragma unroll
                for (int jx = 0; jx < 4; jx++)
                    S[i][jx] += qa[i].x * kb[jx].x + qa[i].y * kb[jx].y +
                                qa[i].z * kb[jx].z + qa[i].w * kb[jx].w;
        }

        // ---- causal mask on diagonal tile
        if (j == qt) {
            #pragma unroll
            for (int i = 0; i < 4; i++)
                #pragma unroll
                for (int jx = 0; jx < 4; jx++)
                    if (tx * 4 + jx > ty * 4 + i) S[i][jx] = -1e30f;
        }

        // ---- online softmax (row spread over 16 tx lanes)
        #pragma unroll
        for (int i = 0; i < 4; i++) {
            float rmax = fmaxf(fmaxf(S[i][0], S[i][1]), fmaxf(S[i][2], S[i][3]));
            #pragma unroll
            for (int m = 8; m >= 1; m >>= 1)
                rmax = fmaxf(rmax, __shfl_xor_sync(0xffffffffu, rmax, m));
            float mnew = fmaxf(mi[i], rmax);
            float sc = __expf(mi[i] - mnew);
            mi[i] = mnew;
            float rsum = 0.f;
            #pragma unroll
            for (int jx = 0; jx < 4; jx++) {
                float p = __expf(S[i][jx] - mnew);
                S[i][jx] = p;
                rsum += p;
            }
            #pragma unroll
            for (int m = 8; m >= 1; m >>= 1)
                rsum += __shfl_xor_sync(0xffffffffu, rsum, m);
            li[i] = li[i] * sc + rsum;
            #pragma unroll
            for (int c = 0; c < 8; c++) o[i][c] *= sc;
            *(float4*)&Psh[(ty * 4 + i) * PSR + tx * 4] =
                make_float4(S[i][0], S[i][1], S[i][2], S[i][3]);
        }
        __syncthreads();

        // ---- O += P @ V  (cols tx*8 .. tx*8+7)
        #pragma unroll 4
        for (int kk4 = 0; kk4 < 16; kk4++) {
            float p[4][4];
            #pragma unroll
            for (int i = 0; i < 4; i++) {
                float4 pa = *(const float4*)&Psh[(ty * 4 + i) * PSR + kk4 * 4];
                p[i][0] = pa.x; p[i][1] = pa.y; p[i][2] = pa.z; p[i][3] = pa.w;
            }
            #pragma unroll
            for (int t = 0; t < 4; t++) {
                float4 v0 = *(const float4*)&Vsh[(kk4 * 4 + t) * VSR + tx * 8];
                float4 v1 = *(const float4*)&Vsh[(kk4 * 4 + t) * VSR + tx * 8 + 4];
                float vv[8] = {v0.x, v0.y, v0.z, v0.w, v1.x, v1.y, v1.z, v1.w};
                #pragma unroll
                for (int i = 0; i < 4; i++)
                    #pragma unroll
                    for (int c = 0; c < 8; c++)
                        o[i][c] += p[i][t] * vv[c];
            }
        }
    }

    // ---- normalize and write out: att[s, hh*128 + col]
    #pragma unroll
    for (int i = 0; i < 4; i++) {
        float inv = 1.f / li[i];
        int s = qt * 64 + ty * 4 + i;
        float4 r0 = make_float4(o[i][0] * inv, o[i][1] * inv, o[i][2] * inv, o[i][3] * inv);
        float4 r1 = make_float4(o[i][4] * inv, o[i][5] * inv, o[i][6] * inv, o[i][7] * inv);
        float* dst = attout + (size_t)s * DMODEL + hh * HDIM + tx * 8;
        *(float4*)dst = r0;
        *(float4*)(dst + 4) = r1;
    }
}

// ---------------- launch ----------------
extern "C" void kernel_launch(void* const* d_in, const int* in_sizes, int n_in,
                              void* d_out, int out_size)
{
    const float* X    = (const float*)d_in[0];   // [2048, 4096]
    const float* cosp = (const float*)d_in[1];   // [2048, 64]
    const float* sinp = (const float*)d_in[2];   // [2048, 64]
    const float* Wd   = (const float*)d_in[3];   // [4096, 2624]
    const float* Wq   = (const float*)d_in[4];   // [1536, 4160]
    const float* Wkv  = (const float*)d_in[5];   // [1024, 8192]
    const float* Wp   = (const float*)d_in[6];   // [4096, 4096]
    float* out = (float*)d_out;                  // [2048, 4096]

    float *h, *qqr, *kvp, *qr, *kr, *att;
    cudaGetSymbolAddress((void**)&h,   g_h);
    cudaGetSymbolAddress((void**)&qqr, g_qqr);
    cudaGetSymbolAddress((void**)&kvp, g_kv);
    cudaGetSymbolAddress((void**)&qr,  g_qr);
    cudaGetSymbolAddress((void**)&kr,  g_kr);
    cudaGetSymbolAddress((void**)&att, g_att);

    cudaFuncSetAttribute(attn_kernel,
                         cudaFuncAttributeMaxDynamicSharedMemorySize, ATTN_SMEM);

    // 1) h = X @ Wd            [2048,2624]
    sgemm_kernel<<<dim3(HCOLS / 64, SEQ / 128), 256>>>(X, DMODEL, Wd, HCOLS, h, HCOLS,
                                                       SEQ, HCOLS, DMODEL);
    // 2) qqr = cq @ Wq         [2048,4160]
    sgemm_kernel<<<dim3(QUPN / 64, SEQ / 128), 256>>>(h, HCOLS, Wq, QUPN, qqr, QUPN,
                                                      SEQ, QUPN, QCD);
    // 3) kv = ckv @ Wkv        [2048,8192]
    sgemm_kernel<<<dim3(KVN / 64, SEQ / 128), 256>>>(h + QCD, HCOLS, Wkv, KVN, kvp, KVN,
                                                     SEQ, KVN, 2 * KCD);
    // 4) RoPE
    rope_kernel<<<SEQ, RDIM>>>(qqr, h, cosp, sinp, qr, kr);
    // 5) attention
    attn_kernel<<<dim3(32, NHEAD), 256, ATTN_SMEM>>>(qqr, kvp, qr, kr, att);
    // 6) out = att @ Wp
    sgemm_kernel<<<dim3(DMODEL / 64, SEQ / 128), 256>>>(att, DMODEL, Wp, DMODEL, out, DMODEL,
                                                        SEQ, DMODEL, DMODEL);
}

// round 3
// speedup vs baseline: 1.6803x; 1.6803x over previous
#include <cuda_runtime.h>
#include <cuda_bf16.h>
#include <cstdint>

#define SEQ   2048
#define DMODEL 4096
#define NHEAD 32
#define HDIM  128
#define QCD   1536
#define KCD   512
#define RDIM  64
#define HCOLS (QCD + 2*KCD + RDIM)   // 2624
#define QUPN  (DMODEL + RDIM)        // 4160
#define KVN   (2*DMODEL)             // 8192
#define ATT_SCALE 0.07216878364870323f

// ---------------- scratch (device globals; no runtime allocation) ----------------
__device__ float g_h  [SEQ * HCOLS];
__device__ float g_qqr[SEQ * QUPN];
__device__ float g_kv [SEQ * KVN];
__device__ float g_qr [SEQ * RDIM];
__device__ float g_kr [SEQ * RDIM];
__device__ float g_att[SEQ * DMODEL];

// ======================= split-bf16 tensor-core GEMM =======================
// C[M,N] = A[M,K] @ B[K,N], fp32 row-major. Each operand split x = hi + lo (bf16);
// C = Ahi*Bhi + Ahi*Blo + Alo*Bhi (fp32 accum). Error ~2^-16.
// Block 128x64x32, 256 thr (8 warps, 4x2 grid of 32x32 warp tiles).
// Requires M%128==0, N%64==0, K%32==0 (true for all four calls).

#define BM 128
#define BN 64
#define BK 32
#define ASTR (BK + 8)   // 40 bf16 = 80B row stride: 16B-aligned, ldmatrix conflict-free
#define BSTR (BN + 8)   // 72 bf16 = 144B row stride

__device__ __forceinline__ uint32_t smem_u32(const void* p) {
    return (uint32_t)__cvta_generic_to_shared(p);
}

__device__ __forceinline__ void ldsm_x4(uint32_t& r0, uint32_t& r1, uint32_t& r2, uint32_t& r3,
                                        uint32_t addr) {
    asm volatile("ldmatrix.sync.aligned.m8n8.x4.shared.b16 {%0,%1,%2,%3}, [%4];"
                 : "=r"(r0), "=r"(r1), "=r"(r2), "=r"(r3) : "r"(addr));
}
__device__ __forceinline__ void ldsm_x4t(uint32_t& r0, uint32_t& r1, uint32_t& r2, uint32_t& r3,
                                         uint32_t addr) {
    asm volatile("ldmatrix.sync.aligned.m8n8.x4.trans.shared.b16 {%0,%1,%2,%3}, [%4];"
                 : "=r"(r0), "=r"(r1), "=r"(r2), "=r"(r3) : "r"(addr));
}
__device__ __forceinline__ void mma16816(float* c, const uint32_t* a, uint32_t b0, uint32_t b1) {
    asm volatile("mma.sync.aligned.m16n8k16.row.col.f32.bf16.bf16.f32 "
                 "{%0,%1,%2,%3}, {%4,%5,%6,%7}, {%8,%9}, {%0,%1,%2,%3};"
                 : "+f"(c[0]), "+f"(c[1]), "+f"(c[2]), "+f"(c[3])
                 : "r"(a[0]), "r"(a[1]), "r"(a[2]), "r"(a[3]), "r"(b0), "r"(b1));
}

__device__ __forceinline__ void store_split(__nv_bfloat16* hi, __nv_bfloat16* lo, float4 v) {
    __nv_bfloat16 h0 = __float2bfloat16_rn(v.x);
    __nv_bfloat16 h1 = __float2bfloat16_rn(v.y);
    __nv_bfloat16 h2 = __float2bfloat16_rn(v.z);
    __nv_bfloat16 h3 = __float2bfloat16_rn(v.w);
    __nv_bfloat162 hA; hA.x = h0; hA.y = h1;
    __nv_bfloat162 hB; hB.x = h2; hB.y = h3;
    *(__nv_bfloat162*)hi       = hA;
    *(__nv_bfloat162*)(hi + 2) = hB;
    __nv_bfloat162 lA, lB;
    lA.x = __float2bfloat16_rn(v.x - __bfloat162float(h0));
    lA.y = __float2bfloat16_rn(v.y - __bfloat162float(h1));
    lB.x = __float2bfloat16_rn(v.z - __bfloat162float(h2));
    lB.y = __float2bfloat16_rn(v.w - __bfloat162float(h3));
    *(__nv_bfloat162*)lo       = lA;
    *(__nv_bfloat162*)(lo + 2) = lB;
}

__global__ void __launch_bounds__(256)
gemm_bf16x3(const float* __restrict__ A, int lda,
            const float* __restrict__ B, int ldb,
            float* __restrict__ C, int ldc, int K)
{
    __shared__ __nv_bfloat16 sAhi[BM][ASTR];
    __shared__ __nv_bfloat16 sAlo[BM][ASTR];
    __shared__ __nv_bfloat16 sBhi[BK][BSTR];
    __shared__ __nv_bfloat16 sBlo[BK][BSTR];

    const int tid  = threadIdx.x;
    const int lane = tid & 31;
    const int wid  = tid >> 5;
    const int wm   = wid & 3;      // 0..3
    const int wn   = wid >> 2;     // 0..1
    const int bm   = blockIdx.y * BM;
    const int bn   = blockIdx.x * BN;

    // A loader: 4 float4/thread, rows (tid>>3)+32i, col quad tid&7
    const int a_c4 = tid & 7;
    const int a_r0 = tid >> 3;
    // B loader: 2 float4/thread, rows (tid>>4)+16i, col quad tid&15
    const int b_c4 = tid & 15;
    const int b_r0 = tid >> 4;

    const float* Aptr = A + (size_t)(bm + a_r0) * lda + a_c4 * 4;
    const float* Bptr = B + (size_t)b_r0 * ldb + bn + b_c4 * 4;

    float4 aReg[4], bReg[2];
    #pragma unroll
    for (int i = 0; i < 4; i++) aReg[i] = *(const float4*)(Aptr + (size_t)(32 * i) * lda);
    #pragma unroll
    for (int i = 0; i < 2; i++) bReg[i] = *(const float4*)(Bptr + (size_t)(16 * i) * ldb);

    float acc[2][4][4];
    #pragma unroll
    for (int mi = 0; mi < 2; mi++)
        #pragma unroll
        for (int ni = 0; ni < 4; ni++)
            #pragma unroll
            for (int r = 0; r < 4; r++) acc[mi][ni][r] = 0.f;

    for (int k0 = 0; k0 < K; k0 += BK) {
        // stage current tile (with hi/lo split)
        #pragma unroll
        for (int i = 0; i < 4; i++) {
            int r = a_r0 + 32 * i;
            store_split(&sAhi[r][a_c4 * 4], &sAlo[r][a_c4 * 4], aReg[i]);
        }
        #pragma unroll
        for (int i = 0; i < 2; i++) {
            int r = b_r0 + 16 * i;
            store_split(&sBhi[r][b_c4 * 4], &sBlo[r][b_c4 * 4], bReg[i]);
        }
        __syncthreads();

        // prefetch next tile
        if (k0 + BK < K) {
            #pragma unroll
            for (int i = 0; i < 4; i++)
                aReg[i] = *(const float4*)(Aptr + (size_t)(32 * i) * lda + (k0 + BK));
            #pragma unroll
            for (int i = 0; i < 2; i++)
                bReg[i] = *(const float4*)(Bptr + (size_t)(16 * i + k0 + BK) * ldb);
        }

        // compute: 2 k16 steps
        #pragma unroll
        for (int ks = 0; ks < 2; ks++) {
            uint32_t ahi[2][4], alo[2][4], bhi[2][4], blo[2][4];
            const int arow = lane & 15;
            const int acol = ks * 16 + (lane >> 4) * 8;
            #pragma unroll
            for (int mi = 0; mi < 2; mi++) {
                int rr = wm * 32 + mi * 16 + arow;
                ldsm_x4(ahi[mi][0], ahi[mi][1], ahi[mi][2], ahi[mi][3],
                        smem_u32(&sAhi[rr][acol]));
                ldsm_x4(alo[mi][0], alo[mi][1], alo[mi][2], alo[mi][3],
                        smem_u32(&sAlo[rr][acol]));
            }
            const int ti   = lane >> 3;
            const int brow = ks * 16 + (lane & 7) + (ti & 1) * 8;
            #pragma unroll
            for (int np = 0; np < 2; np++) {
                int bc = wn * 32 + np * 16 + (ti >> 1) * 8;
                ldsm_x4t(bhi[np][0], bhi[np][1], bhi[np][2], bhi[np][3],
                         smem_u32(&sBhi[brow][bc]));
                ldsm_x4t(blo[np][0], blo[np][1], blo[np][2], blo[np][3],
                         smem_u32(&sBlo[brow][bc]));
            }
            #pragma unroll
            for (int mi = 0; mi < 2; mi++)
                #pragma unroll
                for (int ni = 0; ni < 4; ni++) {
                    int np = ni >> 1, ho = (ni & 1) * 2;
                    uint32_t b0h = bhi[np][ho], b1h = bhi[np][ho + 1];
                    uint32_t b0l = blo[np][ho], b1l = blo[np][ho + 1];
                    mma16816(acc[mi][ni], ahi[mi], b0h, b1h);
                    mma16816(acc[mi][ni], alo[mi], b0h, b1h);
                    mma16816(acc[mi][ni], ahi[mi], b0l, b1l);
                }
        }
        __syncthreads();
    }

    // epilogue
    #pragma unroll
    for (int mi = 0; mi < 2; mi++) {
        int r = bm + wm * 32 + mi * 16 + (lane >> 2);
        #pragma unroll
        for (int ni = 0; ni < 4; ni++) {
            int c = bn + wn * 32 + ni * 8 + (lane & 3) * 2;
            *(float2*)&C[(size_t)r * ldc + c]       = make_float2(acc[mi][ni][0], acc[mi][ni][1]);
            *(float2*)&C[(size_t)(r + 8) * ldc + c] = make_float2(acc[mi][ni][2], acc[mi][ni][3]);
        }
    }
}

// ---------------- RoPE ----------------
__global__ void rope_kernel(const float* __restrict__ qqr,
                            const float* __restrict__ h,
                            const float* __restrict__ cosp,
                            const float* __restrict__ sinp,
                            float* __restrict__ qr,
                            float* __restrict__ kr)
{
    int s = blockIdx.x;
    int i = threadIdx.x;
    float c  = cosp[s * RDIM + i];
    float sv = sinp[s * RDIM + i];
    const float* qsrc = qqr + (size_t)s * QUPN + DMODEL;
    const float* ksrc = h   + (size_t)s * HCOLS + (QCD + 2 * KCD);
    float xq = qsrc[i];
    float xk = ksrc[i];
    float rq = (i < 32) ? -qsrc[i + 32] : qsrc[i - 32];
    float rk = (i < 32) ? -ksrc[i + 32] : ksrc[i - 32];
    qr[s * RDIM + i] = xq * c + rq * sv;
    kr[s * RDIM + i] = xk * c + rk * sv;
}

// ---------------- flash attention, fp32, causal, dq=192 dv=128 ----------------
#define QS 196
#define VSR 132
#define PSR 68
#define ATTN_SMEM ((64*QS*2 + 64*VSR + 64*PSR) * 4)

__global__ void __launch_bounds__(256)
attn_kernel(const float* __restrict__ qqr,
            const float* __restrict__ kv,
            const float* __restrict__ qr,
            const float* __restrict__ kr,
            float* __restrict__ attout)
{
    extern __shared__ float smem[];
    float* Qs  = smem;
    float* Ks  = Qs  + 64 * QS;
    float* Vsh = Ks  + 64 * QS;
    float* Psh = Vsh + 64 * VSR;

    const int qt  = 31 - blockIdx.x;
    const int hh  = blockIdx.y;
    const int tid = threadIdx.x;
    const int tx  = tid & 15;
    const int ty  = tid >> 4;

    for (int idx = tid; idx < 64 * 48; idx += 256) {
        int r  = idx / 48;
        int c4 = idx % 48;
        int s  = qt * 64 + r;
        float4 v;
        if (c4 < 32) v = *(const float4*)(qqr + (size_t)s * QUPN + hh * HDIM + c4 * 4);
        else         v = *(const float4*)(qr + (size_t)s * RDIM + (c4 - 32) * 4);
        v.x *= ATT_SCALE; v.y *= ATT_SCALE; v.z *= ATT_SCALE; v.w *= ATT_SCALE;
        *(float4*)&Qs[r * QS + c4 * 4] = v;
    }

    float o[4][8];
    #pragma unroll
    for (int i = 0; i < 4; i++)
        #pragma unroll
        for (int c = 0; c < 8; c++) o[i][c] = 0.f;
    float mi[4] = {-1e30f, -1e30f, -1e30f, -1e30f};
    float li[4] = {0.f, 0.f, 0.f, 0.f};

    for (int j = 0; j <= qt; j++) {
        __syncthreads();
        for (int idx = tid; idx < 64 * 48; idx += 256) {
            int r  = idx / 48;
            int c4 = idx % 48;
            int s  = j * 64 + r;
            float4 v;
            if (c4 < 32) v = *(const float4*)(kv + (size_t)s * KVN + hh * HDIM + c4 * 4);
            else         v = *(const float4*)(kr + (size_t)s * RDIM + (c4 - 32) * 4);
            *(float4*)&Ks[r * QS + c4 * 4] = v;
        }
        for (int idx = tid; idx < 64 * 32; idx += 256) {
            int r  = idx / 32;
            int c4 = idx % 32;
            int s  = j * 64 + r;
            *(float4*)&Vsh[r * VSR + c4 * 4] =
                *(const float4*)(kv + (size_t)s * KVN + DMODEL + hh * HDIM + c4 * 4);
        }
        __syncthreads();

        float S[4][4];
        #pragma unroll
        for (int i = 0; i < 4; i++)
            #pragma unroll
            for (int jx = 0; jx < 4; jx++) S[i][jx] = 0.f;

        #pragma unroll 4
        for (int kk = 0; kk < 48; kk++) {
            float4 qa[4], kb[4];
            #pragma unroll
            for (int i = 0; i < 4; i++)
                qa[i] = *(const float4*)&Qs[(ty * 4 + i) * QS + kk * 4];
            #pragma unroll
            for (int jx = 0; jx < 4; jx++)
                kb[jx] = *(const float4*)&Ks[(tx * 4 + jx) * QS + kk * 4];
            #pragma unroll
            for (int i = 0; i < 4; i++)
                #pragma unroll
                for (int jx = 0; jx < 4; jx++)
                    S[i][jx] += qa[i].x * kb[jx].x + qa[i].y * kb[jx].y +
                                qa[i].z * kb[jx].z + qa[i].w * kb[jx].w;
        }

        if (j == qt) {
            #pragma unroll
            for (int i = 0; i < 4; i++)
                #pragma unroll
                for (int jx = 0; jx < 4; jx++)
                    if (tx * 4 + jx > ty * 4 + i) S[i][jx] = -1e30f;
        }

        #pragma unroll
        for (int i = 0; i < 4; i++) {
            float rmax = fmaxf(fmaxf(S[i][0], S[i][1]), fmaxf(S[i][2], S[i][3]));
            #pragma unroll
            for (int m = 8; m >= 1; m >>= 1)
                rmax = fmaxf(rmax, __shfl_xor_sync(0xffffffffu, rmax, m));
            float mnew = fmaxf(mi[i], rmax);
            float sc = __expf(mi[i] - mnew);
            mi[i] = mnew;
            float rsum = 0.f;
            #pragma unroll
            for (int jx = 0; jx < 4; jx++) {
                float p = __expf(S[i][jx] - mnew);
                S[i][jx] = p;
                rsum += p;
            }
            #pragma unroll
            for (int m = 8; m >= 1; m >>= 1)
                rsum += __shfl_xor_sync(0xffffffffu, rsum, m);
            li[i] = li[i] * sc + rsum;
            #pragma unroll
            for (int c = 0; c < 8; c++) o[i][c] *= sc;
            *(float4*)&Psh[(ty * 4 + i) * PSR + tx * 4] =
                make_float4(S[i][0], S[i][1], S[i][2], S[i][3]);
        }
        __syncthreads();

        #pragma unroll 4
        for (int kk4 = 0; kk4 < 16; kk4++) {
            float p[4][4];
            #pragma unroll
            for (int i = 0; i < 4; i++) {
                float4 pa = *(const float4*)&Psh[(ty * 4 + i) * PSR + kk4 * 4];
                p[i][0] = pa.x; p[i][1] = pa.y; p[i][2] = pa.z; p[i][3] = pa.w;
            }
            #pragma unroll
            for (int t = 0; t < 4; t++) {
                float4 v0 = *(const float4*)&Vsh[(kk4 * 4 + t) * VSR + tx * 8];
                float4 v1 = *(const float4*)&Vsh[(kk4 * 4 + t) * VSR + tx * 8 + 4];
                float vv[8] = {v0.x, v0.y, v0.z, v0.w, v1.x, v1.y, v1.z, v1.w};
                #pragma unroll
                for (int i = 0; i < 4; i++)
                    #pragma unroll
                    for (int c = 0; c < 8; c++)
                        o[i][c] += p[i][t] * vv[c];
            }
        }
    }

    #pragma unroll
    for (int i = 0; i < 4; i++) {
        float inv = 1.f / li[i];
        int s = qt * 64 + ty * 4 + i;
        float4 r0 = make_float4(o[i][0] * inv, o[i][1] * inv, o[i][2] * inv, o[i][3] * inv);
        float4 r1 = make_float4(o[i][4] * inv, o[i][5] * inv, o[i][6] * inv, o[i][7] * inv);
        float* dst = attout + (size_t)s * DMODEL + hh * HDIM + tx * 8;
        *(float4*)dst = r0;
        *(float4*)(dst + 4) = r1;
    }
}

// ---------------- launch ----------------
extern "C" void kernel_launch(void* const* d_in, const int* in_sizes, int n_in,
                              void* d_out, int out_size)
{
    const float* X    = (const float*)d_in[0];
    const float* cosp = (const float*)d_in[1];
    const float* sinp = (const float*)d_in[2];
    const float* Wd   = (const float*)d_in[3];
    const float* Wq   = (const float*)d_in[4];
    const float* Wkv  = (const float*)d_in[5];
    const float* Wp   = (const float*)d_in[6];
    float* out = (float*)d_out;

    float *h, *qqr, *kvp, *qr, *kr, *att;
    cudaGetSymbolAddress((void**)&h,   g_h);
    cudaGetSymbolAddress((void**)&qqr, g_qqr);
    cudaGetSymbolAddress((void**)&kvp, g_kv);
    cudaGetSymbolAddress((void**)&qr,  g_qr);
    cudaGetSymbolAddress((void**)&kr,  g_kr);
    cudaGetSymbolAddress((void**)&att, g_att);

    cudaFuncSetAttribute(attn_kernel,
                         cudaFuncAttributeMaxDynamicSharedMemorySize, ATTN_SMEM);

    // 1) h = X @ Wd
    gemm_bf16x3<<<dim3(HCOLS / BN, SEQ / BM), 256>>>(X, DMODEL, Wd, HCOLS, h, HCOLS, DMODEL);
    // 2) qqr = cq @ Wq
    gemm_bf16x3<<<dim3(QUPN / BN, SEQ / BM), 256>>>(h, HCOLS, Wq, QUPN, qqr, QUPN, QCD);
    // 3) kv = ckv @ Wkv
    gemm_bf16x3<<<dim3(KVN / BN, SEQ / BM), 256>>>(h + QCD, HCOLS, Wkv, KVN, kvp, KVN, 2 * KCD);
    // 4) RoPE
    rope_kernel<<<SEQ, RDIM>>>(qqr, h, cosp, sinp, qr, kr);
    // 5) attention
    attn_kernel<<<dim3(32, NHEAD), 256, ATTN_SMEM>>>(qqr, kvp, qr, kr, att);
    // 6) out = att @ Wp
    gemm_bf16x3<<<dim3(DMODEL / BN, SEQ / BM), 256>>>(att, DMODEL, Wp, DMODEL, out, DMODEL, DMODEL);
}